// round 6
// baseline (speedup 1.0000x reference)
#include <cuda_runtime.h>
#include <cuda_bf16.h>

// PointPillarsScatter: out[b, c, y, x] = feat[n, c] where coords[n] = (b, _, y, x), else 0.
// Inverse-index gather with SELF-VALIDATING map (no memset needed):
//   g_map is a __device__ global (zero-initialized). scatter writes pillar index n
//   into g_map[b,y,x]. Entries are therefore always either 0 (never written) or a
//   correct index, so the write kernel validates an entry m by checking
//   coords[m] == (b,_,y,x). Empty cells hold 0 -> validation reads coords[0]
//   (broadcast, cache-hit) and fails the match.
// Write kernel emits the 219MB output exactly once: each thread owns 8 consecutive
// x cells x 16 channels; warps write 1KB contiguous spans with float4 streaming stores.

#define NYd 496
#define NXd 432
#define Cd  64
#define Bd  4
#define HWd (NYd * NXd)          // 214272
#define MAPN (Bd * HWd)          // 857088 ints, 3.4 MB scratch (zero-init)

__device__ int g_map[MAPN];

// ---- Kernel 1: scatter pillar index into map ----
__global__ void scatter_map_kernel(const int* __restrict__ coords, int n_total) {
    int n = blockIdx.x * blockDim.x + threadIdx.x;
    if (n >= n_total) return;
    int4 cc = ((const int4*)coords)[n];   // (b, z, y, x)
    g_map[(cc.x * NYd + cc.z) * NXd + cc.w] = n;
}

// ---- Kernel 2: gather-write output, coalesced float4 streaming stores ----
// One thread per (quarter, b, y, x/8); 16 channels per thread. 'quarter' is the
// outermost (slow) dimension so tid walks each (b,c)-plane contiguously:
// a warp's 2 stores/iter cover 1KB of contiguous memory.
__global__ void __launch_bounds__(256) write_out_kernel(
        const float* __restrict__ feat, const int4* __restrict__ coords,
        float* __restrict__ out, int n_total) {
    const int XV = NXd / 8;  // 54
    const int CQ = Cd / 4;   // 16 channels per thread
    int tid = blockIdx.x * blockDim.x + threadIdx.x;
    if (tid >= 4 * Bd * NYd * XV) return;

    int t  = tid;
    int x8 = t % XV;  t /= XV;
    int y  = t % NYd; t /= NYd;
    int b  = t % Bd;
    int q  = t / Bd;            // 0..3
    int c0 = q * CQ;            // 0,16,32,48

    const int* mp = &g_map[(b * NYd + y) * NXd + x8 * 8];
    int m[8];
    *(int4*)&m[0] = *(const int4*)mp;
    *(int4*)&m[4] = *(const int4*)(mp + 4);

    bool ok[8];
    int  o[8];
    #pragma unroll
    for (int j = 0; j < 8; j++) {
        int mj = m[j];
        bool v = ((unsigned)mj < (unsigned)n_total);
        if (v) {
            int4 cc = __ldg(&coords[mj]);          // empty cells: coords[0], L1-hit
            v = (cc.x == b) & (cc.z == y) & (cc.w == x8 * 8 + j);
        }
        ok[j] = v;
        o[j]  = mj * Cd + c0;                      // 32-bit offsets, < 2^31
    }

    // out offset for channel c: ((b*C + c0 + c)*NY + y)*NX + x
    float* outp = out + ((b * Cd + c0) * NYd + y) * NXd + x8 * 8;

    #pragma unroll
    for (int c = 0; c < CQ; c++) {
        float4 va, vb;
        va.x = ok[0] ? __ldg(feat + o[0] + c) : 0.0f;
        va.y = ok[1] ? __ldg(feat + o[1] + c) : 0.0f;
        va.z = ok[2] ? __ldg(feat + o[2] + c) : 0.0f;
        va.w = ok[3] ? __ldg(feat + o[3] + c) : 0.0f;
        vb.x = ok[4] ? __ldg(feat + o[4] + c) : 0.0f;
        vb.y = ok[5] ? __ldg(feat + o[5] + c) : 0.0f;
        vb.z = ok[6] ? __ldg(feat + o[6] + c) : 0.0f;
        vb.w = ok[7] ? __ldg(feat + o[7] + c) : 0.0f;
        float4* p = (float4*)(outp + c * HWd);
        __stcs(p,     va);
        __stcs(p + 1, vb);
    }
}

extern "C" void kernel_launch(void* const* d_in, const int* in_sizes, int n_in,
                              void* d_out, int out_size) {
    const float* feat   = (const float*)d_in[0];
    const int*   coords = (const int*)d_in[1];
    int n_total = in_sizes[1] / 4;

    // 1) map[idx] = n  (no memset: zero-init + validation handles empty cells)
    scatter_map_kernel<<<(n_total + 255) / 256, 256>>>(coords, n_total);

    // 2) gather-write full output (4 threads per cell-octet: 16 channels each)
    {
        int nthreads = 4 * Bd * NYd * (NXd / 8);   // 428544
        write_out_kernel<<<(nthreads + 255) / 256, 256>>>(
            feat, (const int4*)coords, (float*)d_out, n_total);
    }
}